// round 1
// baseline (speedup 1.0000x reference)
#include <cuda_runtime.h>
#include <math.h>

// Problem constants
#define MB_ 8192   // batch B
#define HD  768    // hidden H
#define KD  768    // reduction dim

// ---------------- scratch (device globals; no allocation allowed) ----------
__device__ float g_t1m[MB_ * HD];    // tanh(A@W1m^T + b1m)
__device__ float g_t1v[MB_ * HD];    // tanh(A@W1v^T + b1v)
__device__ float g_mu [MB_ * HD];    // mu
__device__ float g_iv [MB_ * HD];    // exp(-tanh(...)) = inv_var
__device__ float g_psum[32 * HD];    // partial column sums of mu
__device__ float g_psq [32 * HD];    // partial column sums of mu^2
__device__ float g_mean[HD];         // mu_mean
__device__ float g_sqm [HD];         // mu_sq_mean
__device__ float g_ppos[512];        // per-block positive partials
__device__ float g_pneg[512];        // per-block negative partials

// ---------------- GEMM: C[M,N] = A[M,K] @ W[N,K]^T + bias, epilogue ---------
// EPI: 0 = none, 1 = tanh, 2 = exp(-tanh(x))
// Tiles: BM=BN=128, BK=16, 256 threads, 8x8 microtile per thread (split 4+4).
template <int EPI>
__global__ void __launch_bounds__(256)
gemm_nt(const float* __restrict__ A, const float* __restrict__ W,
        const float* __restrict__ bias, float* __restrict__ C)
{
    constexpr int BK = 16;
    __shared__ float As[BK][128];
    __shared__ float Ws[BK][128];

    const int bm  = blockIdx.y * 128;
    const int bn  = blockIdx.x * 128;
    const int tid = threadIdx.x;
    const int tx  = tid & 15;   // n direction (16)
    const int ty  = tid >> 4;   // m direction (16)

    float acc[8][8];
#pragma unroll
    for (int i = 0; i < 8; i++)
#pragma unroll
        for (int j = 0; j < 8; j++) acc[i][j] = 0.f;

    const float* Ag = A + (size_t)bm * KD;
    const float* Wg = W + (size_t)bn * KD;

    for (int k0 = 0; k0 < KD; k0 += BK) {
        // Load 128x16 tiles of A and W, transposed into smem [k][m/n].
        // 512 float4 per tile, 2 per thread.
#pragma unroll
        for (int r = 0; r < 2; r++) {
            int idx = tid + 256 * r;          // 0..511
            int row = idx >> 2;               // 0..127
            int c4  = (idx & 3) << 2;         // 0,4,8,12
            float4 av = *(const float4*)(Ag + (size_t)row * KD + k0 + c4);
            As[c4 + 0][row] = av.x; As[c4 + 1][row] = av.y;
            As[c4 + 2][row] = av.z; As[c4 + 3][row] = av.w;
            float4 wv = *(const float4*)(Wg + (size_t)row * KD + k0 + c4);
            Ws[c4 + 0][row] = wv.x; Ws[c4 + 1][row] = wv.y;
            Ws[c4 + 2][row] = wv.z; Ws[c4 + 3][row] = wv.w;
        }
        __syncthreads();

#pragma unroll
        for (int k = 0; k < BK; k++) {
            float4 a0 = *(const float4*)&As[k][ty * 4];
            float4 a1 = *(const float4*)&As[k][64 + ty * 4];
            float4 w0 = *(const float4*)&Ws[k][tx * 4];
            float4 w1 = *(const float4*)&Ws[k][64 + tx * 4];
            float af[8] = {a0.x, a0.y, a0.z, a0.w, a1.x, a1.y, a1.z, a1.w};
            float wf[8] = {w0.x, w0.y, w0.z, w0.w, w1.x, w1.y, w1.z, w1.w};
#pragma unroll
            for (int i = 0; i < 8; i++)
#pragma unroll
                for (int j = 0; j < 8; j++)
                    acc[i][j] = fmaf(af[i], wf[j], acc[i][j]);
        }
        __syncthreads();
    }

#pragma unroll
    for (int i = 0; i < 8; i++) {
        int m = bm + ((i < 4) ? (ty * 4 + i) : (64 + ty * 4 + i - 4));
#pragma unroll
        for (int j = 0; j < 8; j++) {
            int n = bn + ((j < 4) ? (tx * 4 + j) : (64 + tx * 4 + j - 4));
            float v = acc[i][j] + bias[n];
            if (EPI == 1)      v = tanhf(v);
            else if (EPI == 2) v = __expf(-tanhf(v));
            C[(size_t)m * HD + n] = v;
        }
    }
}

// ---------------- column-mean reductions over B (deterministic, 2-stage) ---
__global__ void colsum_partial()
{
    int h  = blockIdx.x * 256 + threadIdx.x;   // gridDim.x = 3  (768 cols)
    int bi = blockIdx.y;                       // 32 row-chunks of 256
    int r0 = bi * 256;
    float s = 0.f, q = 0.f;
    for (int r = 0; r < 256; r++) {
        float v = g_mu[(size_t)(r0 + r) * HD + h];
        s += v;
        q += v * v;
    }
    g_psum[bi * HD + h] = s;
    g_psq [bi * HD + h] = q;
}

__global__ void colsum_final()
{
    int h = blockIdx.x * 256 + threadIdx.x;    // 3 blocks
    float s = 0.f, q = 0.f;
#pragma unroll
    for (int b = 0; b < 32; b++) {
        s += g_psum[b * HD + h];
        q += g_psq [b * HD + h];
    }
    g_mean[h] = s * (1.0f / MB_);
    g_sqm [h] = q * (1.0f / MB_);
}

// ---------------- fused positive/negative reduction ------------------------
__global__ void __launch_bounds__(256)
pos_neg_partial(const float* __restrict__ modal_b)
{
    constexpr int CH = (MB_ * HD) / 512;       // 12288, multiple of HD chunkable
    int base = blockIdx.x * CH;                // base % HD == 0 (12288 = 16*768)
    float p = 0.f, nn = 0.f;
    for (int i = threadIdx.x; i < CH; i += 256) {
        int idx = base + i;
        int h   = i % HD;
        float m  = g_mu[idx];
        float iv = g_iv[idx];
        float b  = modal_b[idx];
        float d  = m - b;
        p += d * d * iv;                                   // (mu-b)^2 * inv_var
        float pair = g_sqm[h] - 2.f * m * g_mean[h] + m * m;
        nn += pair * iv;
    }
    __shared__ float sp[256], sn[256];
    sp[threadIdx.x] = p; sn[threadIdx.x] = nn;
    __syncthreads();
    for (int s = 128; s > 0; s >>= 1) {
        if (threadIdx.x < s) {
            sp[threadIdx.x] += sp[threadIdx.x + s];
            sn[threadIdx.x] += sn[threadIdx.x + s];
        }
        __syncthreads();
    }
    if (threadIdx.x == 0) {
        g_ppos[blockIdx.x] = sp[0];
        g_pneg[blockIdx.x] = sn[0];
    }
}

__global__ void finalize(float* __restrict__ out)
{
    __shared__ float sp[256], sn[256];
    int t = threadIdx.x;
    sp[t] = g_ppos[t] + g_ppos[t + 256];
    sn[t] = g_pneg[t] + g_pneg[t + 256];
    __syncthreads();
    for (int s = 128; s > 0; s >>= 1) {
        if (t < s) { sp[t] += sp[t + s]; sn[t] += sn[t + s]; }
        __syncthreads();
    }
    if (t == 0) {
        float P = sp[0], Nn = sn[0];
        out[0] = -0.5f * P / (float)MB_;             // lld
        out[1] = 0.5f * (Nn - P) / (float)MB_;       // bound
    }
}

// ---------------- launch ----------------------------------------------------
extern "C" void kernel_launch(void* const* d_in, const int* in_sizes, int n_in,
                              void* d_out, int out_size)
{
    const float* A   = (const float*)d_in[0];   // modal_a [B,H]
    const float* Mb  = (const float*)d_in[1];   // modal_b [B,H]
    const float* W1m = (const float*)d_in[2];
    const float* b1m = (const float*)d_in[3];
    const float* W2m = (const float*)d_in[4];
    const float* b2m = (const float*)d_in[5];
    const float* W1v = (const float*)d_in[6];
    const float* b1v = (const float*)d_in[7];
    const float* W2v = (const float*)d_in[8];
    const float* b2v = (const float*)d_in[9];

    float *t1m, *t1v, *mu, *iv;
    cudaGetSymbolAddress((void**)&t1m, g_t1m);
    cudaGetSymbolAddress((void**)&t1v, g_t1v);
    cudaGetSymbolAddress((void**)&mu,  g_mu);
    cudaGetSymbolAddress((void**)&iv,  g_iv);

    dim3 grid(HD / 128, MB_ / 128);   // (6, 64)

    gemm_nt<1><<<grid, 256>>>(A,   W1m, b1m, t1m);   // tanh epilogue
    gemm_nt<1><<<grid, 256>>>(A,   W1v, b1v, t1v);   // tanh epilogue
    gemm_nt<0><<<grid, 256>>>(t1m, W2m, b2m, mu);    // mu = linear
    gemm_nt<2><<<grid, 256>>>(t1v, W2v, b2v, iv);    // inv_var = exp(-tanh(.))

    colsum_partial<<<dim3(3, 32), 256>>>();
    colsum_final  <<<3, 256>>>();
    pos_neg_partial<<<512, 256>>>(Mb);
    finalize<<<1, 256>>>((float*)d_out);
}

// round 3
// speedup vs baseline: 5.4095x; 5.4095x over previous
#include <cuda_runtime.h>
#include <cuda_bf16.h>
#include <cstdint>
#include <math.h>

// ---------------------------------------------------------------------------
#define MB_ 8192   // batch B
#define HD  768    // hidden H (= K dim)

__device__ __forceinline__ uint32_t smem_to_u32(const void* smem_ptr) {
    uint32_t addr;
    asm("{ .reg .u64 tmp; cvta.to.shared.u64 tmp, %1; cvt.u32.u64 %0, tmp; }"
        : "=r"(addr) : "l"(smem_ptr));
    return addr;
}

// ---------------------------------------------------------------------------
// scratch (device globals; no allocation allowed)
__device__ __nv_bfloat16 g_abf [MB_ * HD];
__device__ __nv_bfloat16 g_w1m [HD * HD];
__device__ __nv_bfloat16 g_w2m [HD * HD];
__device__ __nv_bfloat16 g_w1v [HD * HD];
__device__ __nv_bfloat16 g_w2v [HD * HD];
__device__ __nv_bfloat16 g_t1m [MB_ * HD];
__device__ __nv_bfloat16 g_t1v [MB_ * HD];
__device__ float g_mu [MB_ * HD];
__device__ float g_iv [MB_ * HD];
__device__ float g_psum[32 * HD];
__device__ float g_psq [32 * HD];
__device__ float g_mean[HD];
__device__ float g_sqm [HD];
__device__ float g_ppos[512];
__device__ float g_pneg[512];

// ---------------------------------------------------------------------------
__global__ void cvt_f32_bf16(const float* __restrict__ src,
                             __nv_bfloat16* __restrict__ dst)
{
    size_t i = ((size_t)blockIdx.x * 256 + threadIdx.x) * 4;
    float4 v = *(const float4*)(src + i);
    __nv_bfloat162 lo = __floats2bfloat162_rn(v.x, v.y);
    __nv_bfloat162 hi = __floats2bfloat162_rn(v.z, v.w);
    *(uint2*)(dst + i) = make_uint2(*(uint32_t*)&lo, *(uint32_t*)&hi);
}

// ---------------------------------------------------------------------------
// HMMA GEMM: C[M,N] = A[M,768] @ W[N,768]^T + bias, epilogue EPI
// EPI: 0 = none (f32 out), 1 = tanh (bf16 out), 2 = exp(-tanh) (f32 out)
// CTA tile 128x128, BK=64, double-buffered cp.async, 8 warps of 64x32.
// smem: buf0 A 16KB | buf0 W 16KB | buf1 A 16KB | buf1 W 16KB  = 64KB
#define GT_SMEM 65536

__device__ __forceinline__ void ldsm_x4(uint32_t* r, uint32_t addr) {
    asm volatile("ldmatrix.sync.aligned.m8n8.x4.shared.b16 {%0,%1,%2,%3}, [%4];"
                 : "=r"(r[0]), "=r"(r[1]), "=r"(r[2]), "=r"(r[3]) : "r"(addr));
}
__device__ __forceinline__ void ldsm_x2(uint32_t* r, uint32_t addr) {
    asm volatile("ldmatrix.sync.aligned.m8n8.x2.shared.b16 {%0,%1}, [%2];"
                 : "=r"(r[0]), "=r"(r[1]) : "r"(addr));
}
__device__ __forceinline__ void mma_bf16(float* c, const uint32_t* a, const uint32_t* b) {
    asm volatile(
        "mma.sync.aligned.m16n8k16.row.col.f32.bf16.bf16.f32 "
        "{%0,%1,%2,%3}, {%4,%5,%6,%7}, {%8,%9}, {%0,%1,%2,%3};"
        : "+f"(c[0]), "+f"(c[1]), "+f"(c[2]), "+f"(c[3])
        : "r"(a[0]), "r"(a[1]), "r"(a[2]), "r"(a[3]), "r"(b[0]), "r"(b[1]));
}
#define CP_ASYNC16(dst, src) \
    asm volatile("cp.async.cg.shared.global [%0], [%1], 16;" :: "r"(dst), "l"(src))
#define CP_COMMIT() asm volatile("cp.async.commit_group;" ::: "memory")
#define CP_WAIT1()  asm volatile("cp.async.wait_group 1;" ::: "memory")

template <int EPI>
__global__ void __launch_bounds__(256, 2)
gemm_hmma(const __nv_bfloat16* __restrict__ A,
          const __nv_bfloat16* __restrict__ W,
          const float* __restrict__ bias,
          void* __restrict__ Cout)
{
    extern __shared__ char smem[];
    const uint32_t sb = smem_to_u32(smem);
    const int tid  = threadIdx.x;
    const int lane = tid & 31;
    const int wid  = tid >> 5;
    const int wm0  = (wid >> 2) * 64;   // warp m offset (0 or 64)
    const int wn0  = (wid & 3) * 32;    // warp n offset
    const int bm   = blockIdx.y * 128;
    const int bn   = blockIdx.x * 128;

    float acc[4][4][4];
#pragma unroll
    for (int i = 0; i < 4; i++)
#pragma unroll
        for (int j = 0; j < 4; j++)
#pragma unroll
            for (int q = 0; q < 4; q++) acc[i][j][q] = 0.f;

    const __nv_bfloat16* Ag = A + (size_t)bm * HD;
    const __nv_bfloat16* Wg = W + (size_t)bn * HD;

    // per-thread load mapping: 4 chunks per tile (A and W each)
    // idx = r*256+tid; row = idx>>3 (0..127); cg = idx&7 (16B chunk in 128B row)
    // swizzled chunk = cg ^ (row & 7)
    auto load_tiles = [&](int c, int buf) {
        const uint32_t ab = sb + buf * 32768;
        const uint32_t wb = ab + 16384;
        const int k0 = c * 64;
#pragma unroll
        for (int r = 0; r < 4; r++) {
            int idx = r * 256 + tid;
            int row = idx >> 3;
            int cg  = idx & 7;
            uint32_t off = ((uint32_t)row << 7) + ((uint32_t)(cg ^ (row & 7)) << 4);
            CP_ASYNC16(ab + off, Ag + (size_t)row * HD + k0 + cg * 8);
            CP_ASYNC16(wb + off, Wg + (size_t)row * HD + k0 + cg * 8);
        }
    };

    load_tiles(0, 0);
    CP_COMMIT();

    const int axor = lane & 7;                 // (row&7) for both A and B frags
    const int arow = (lane & 15);              // A frag row-in-16 (per lane)
    const int ahi  = lane >> 4;                // A k-halves
    const int brow = (lane & 7);               // B frag row-in-8
    const int bhi  = (lane >> 3) & 1;          // B k-halves

    for (int c = 0; c < 12; c++) {
        const int buf = c & 1;
        if (c < 11) load_tiles(c + 1, buf ^ 1);
        CP_COMMIT();
        CP_WAIT1();
        __syncthreads();

        const uint32_t ab = sb + buf * 32768;
        const uint32_t wb = ab + 16384;
#pragma unroll
        for (int ks = 0; ks < 4; ks++) {
            uint32_t afr[4][4];
#pragma unroll
            for (int mf = 0; mf < 4; mf++) {
                int row = wm0 + mf * 16 + arow;
                uint32_t addr = ab + ((uint32_t)row << 7)
                              + ((uint32_t)((2 * ks + ahi) ^ axor) << 4);
                ldsm_x4(afr[mf], addr);
            }
#pragma unroll
            for (int nf = 0; nf < 4; nf++) {
                int row = wn0 + nf * 8 + brow;
                uint32_t addr = wb + ((uint32_t)row << 7)
                              + ((uint32_t)((2 * ks + bhi) ^ axor) << 4);
                uint32_t bfr[2];
                ldsm_x2(bfr, addr);
#pragma unroll
                for (int mf = 0; mf < 4; mf++)
                    mma_bf16(acc[mf][nf], afr[mf], bfr);
            }
        }
        __syncthreads();
    }

    // epilogue: acc layout per m16n8 frag:
    // c0,c1 -> (row g, col 2t, 2t+1); c2,c3 -> (row g+8, same cols)
    const int g  = lane >> 2;
    const int tq = lane & 3;
#pragma unroll
    for (int mf = 0; mf < 4; mf++) {
#pragma unroll
        for (int nf = 0; nf < 4; nf++) {
            const int m0 = bm + wm0 + mf * 16 + g;
            const int n  = bn + wn0 + nf * 8 + tq * 2;
            const float bv0 = __ldg(&bias[n]);
            const float bv1 = __ldg(&bias[n + 1]);
            float v00 = acc[mf][nf][0] + bv0;
            float v01 = acc[mf][nf][1] + bv1;
            float v10 = acc[mf][nf][2] + bv0;
            float v11 = acc[mf][nf][3] + bv1;
            if (EPI == 1) {
                __nv_bfloat16* C = (__nv_bfloat16*)Cout;
                __nv_bfloat162 p0 = __floats2bfloat162_rn(tanhf(v00), tanhf(v01));
                __nv_bfloat162 p1 = __floats2bfloat162_rn(tanhf(v10), tanhf(v11));
                *(__nv_bfloat162*)&C[(size_t)m0 * HD + n]       = p0;
                *(__nv_bfloat162*)&C[(size_t)(m0 + 8) * HD + n] = p1;
            } else {
                float* C = (float*)Cout;
                if (EPI == 2) {
                    v00 = __expf(-tanhf(v00)); v01 = __expf(-tanhf(v01));
                    v10 = __expf(-tanhf(v10)); v11 = __expf(-tanhf(v11));
                }
                *(float2*)&C[(size_t)m0 * HD + n]       = make_float2(v00, v01);
                *(float2*)&C[(size_t)(m0 + 8) * HD + n] = make_float2(v10, v11);
            }
        }
    }
}

// ---------------------------------------------------------------------------
// column-mean reductions over B (deterministic, 2-stage)
__global__ void colsum_partial()
{
    int h  = blockIdx.x * 256 + threadIdx.x;   // gridDim.x = 3
    int r0 = blockIdx.y * 256;                 // gridDim.y = 32
    float s = 0.f, q = 0.f;
    for (int r = 0; r < 256; r++) {
        float v = g_mu[(size_t)(r0 + r) * HD + h];
        s += v;
        q += v * v;
    }
    g_psum[blockIdx.y * HD + h] = s;
    g_psq [blockIdx.y * HD + h] = q;
}

__global__ void colsum_final()
{
    int h = blockIdx.x * 256 + threadIdx.x;
    float s = 0.f, q = 0.f;
#pragma unroll
    for (int b = 0; b < 32; b++) {
        s += g_psum[b * HD + h];
        q += g_psq [b * HD + h];
    }
    g_mean[h] = s * (1.0f / MB_);
    g_sqm [h] = q * (1.0f / MB_);
}

// ---------------------------------------------------------------------------
__global__ void __launch_bounds__(256)
pos_neg_partial(const float* __restrict__ modal_b)
{
    constexpr int CH = (MB_ * HD) / 512;       // 12288 = 16*768
    int base = blockIdx.x * CH;
    float p = 0.f, nn = 0.f;
    for (int i = threadIdx.x; i < CH; i += 256) {
        int idx = base + i;
        int h   = i % HD;
        float m  = g_mu[idx];
        float iv = g_iv[idx];
        float b  = modal_b[idx];
        float dd = m - b;
        p += dd * dd * iv;
        float pair = g_sqm[h] - 2.f * m * g_mean[h] + m * m;
        nn += pair * iv;
    }
    __shared__ float sp[256], sn[256];
    sp[threadIdx.x] = p; sn[threadIdx.x] = nn;
    __syncthreads();
    for (int s = 128; s > 0; s >>= 1) {
        if (threadIdx.x < s) {
            sp[threadIdx.x] += sp[threadIdx.x + s];
            sn[threadIdx.x] += sn[threadIdx.x + s];
        }
        __syncthreads();
    }
    if (threadIdx.x == 0) {
        g_ppos[blockIdx.x] = sp[0];
        g_pneg[blockIdx.x] = sn[0];
    }
}

__global__ void finalize(float* __restrict__ out)
{
    __shared__ float sp[256], sn[256];
    int t = threadIdx.x;
    sp[t] = g_ppos[t] + g_ppos[t + 256];
    sn[t] = g_pneg[t] + g_pneg[t + 256];
    __syncthreads();
    for (int s = 128; s > 0; s >>= 1) {
        if (t < s) { sp[t] += sp[t + s]; sn[t] += sn[t + s]; }
        __syncthreads();
    }
    if (t == 0) {
        float P = sp[0], Nn = sn[0];
        out[0] = -0.5f * P / (float)MB_;
        out[1] = 0.5f * (Nn - P) / (float)MB_;
    }
}

// ---------------------------------------------------------------------------
extern "C" void kernel_launch(void* const* d_in, const int* in_sizes, int n_in,
                              void* d_out, int out_size)
{
    const float* A   = (const float*)d_in[0];
    const float* Mb  = (const float*)d_in[1];
    const float* W1m = (const float*)d_in[2];
    const float* b1m = (const float*)d_in[3];
    const float* W2m = (const float*)d_in[4];
    const float* b2m = (const float*)d_in[5];
    const float* W1v = (const float*)d_in[6];
    const float* b1v = (const float*)d_in[7];
    const float* W2v = (const float*)d_in[8];
    const float* b2v = (const float*)d_in[9];

    __nv_bfloat16 *abf, *w1m, *w2m, *w1v, *w2v, *t1m, *t1v;
    float *mu, *iv;
    cudaGetSymbolAddress((void**)&abf, g_abf);
    cudaGetSymbolAddress((void**)&w1m, g_w1m);
    cudaGetSymbolAddress((void**)&w2m, g_w2m);
    cudaGetSymbolAddress((void**)&w1v, g_w1v);
    cudaGetSymbolAddress((void**)&w2v, g_w2v);
    cudaGetSymbolAddress((void**)&t1m, g_t1m);
    cudaGetSymbolAddress((void**)&t1v, g_t1v);
    cudaGetSymbolAddress((void**)&mu,  g_mu);
    cudaGetSymbolAddress((void**)&iv,  g_iv);

    cudaFuncSetAttribute(gemm_hmma<0>, cudaFuncAttributeMaxDynamicSharedMemorySize, GT_SMEM);
    cudaFuncSetAttribute(gemm_hmma<1>, cudaFuncAttributeMaxDynamicSharedMemorySize, GT_SMEM);
    cudaFuncSetAttribute(gemm_hmma<2>, cudaFuncAttributeMaxDynamicSharedMemorySize, GT_SMEM);

    cvt_f32_bf16<<<(MB_ * HD) / 4 / 256, 256>>>(A,   abf);
    cvt_f32_bf16<<<(HD  * HD) / 4 / 256, 256>>>(W1m, w1m);
    cvt_f32_bf16<<<(HD  * HD) / 4 / 256, 256>>>(W1v, w1v);
    cvt_f32_bf16<<<(HD  * HD) / 4 / 256, 256>>>(W2m, w2m);
    cvt_f32_bf16<<<(HD  * HD) / 4 / 256, 256>>>(W2v, w2v);

    dim3 grid(HD / 128, MB_ / 128);   // (6, 64)
    gemm_hmma<1><<<grid, 256, GT_SMEM>>>(abf, w1m, b1m, t1m);
    gemm_hmma<1><<<grid, 256, GT_SMEM>>>(abf, w1v, b1v, t1v);
    gemm_hmma<0><<<grid, 256, GT_SMEM>>>(t1m, w2m, b2m, mu);
    gemm_hmma<2><<<grid, 256, GT_SMEM>>>(t1v, w2v, b2v, iv);

    colsum_partial<<<dim3(3, 32), 256>>>();
    colsum_final  <<<3, 256>>>();
    pos_neg_partial<<<512, 256>>>(Mb);
    finalize<<<1, 256>>>((float*)d_out);
}

// round 4
// speedup vs baseline: 6.6014x; 1.2203x over previous
#include <cuda_runtime.h>
#include <cuda_bf16.h>
#include <cstdint>
#include <math.h>

// ---------------------------------------------------------------------------
#define MB_ 8192   // batch B
#define HD  768    // hidden H (= K dim)

__device__ __forceinline__ uint32_t smem_to_u32(const void* smem_ptr) {
    uint32_t addr;
    asm("{ .reg .u64 tmp; cvta.to.shared.u64 tmp, %1; cvt.u32.u64 %0, tmp; }"
        : "=r"(addr) : "l"(smem_ptr));
    return addr;
}

// ---------------------------------------------------------------------------
// scratch (device globals; no allocation allowed)
__device__ __nv_bfloat16 g_abf [MB_ * HD];
__device__ __nv_bfloat16 g_w1m [HD * HD];
__device__ __nv_bfloat16 g_w1v [HD * HD];
__device__ __nv_bfloat16 g_w2m [HD * HD];
__device__ __nv_bfloat16 g_w2v [HD * HD];
__device__ __nv_bfloat16 g_t1m [MB_ * HD];
__device__ __nv_bfloat16 g_t1v [MB_ * HD];
__device__ float g_mu  [MB_ * HD];
__device__ float g_psum[64 * HD];   // per (m-block, col) partial sums of mu
__device__ float g_psq [64 * HD];
__device__ float g_mean[HD];
__device__ float g_sqm [HD];
__device__ float g_ppos[384];
__device__ float g_pneg[384];

// ---------------------------------------------------------------------------
// all fp32->bf16 conversions in one launch
__global__ void cvt_all(const float* __restrict__ A,
                        const float* __restrict__ W1m, const float* __restrict__ W1v,
                        const float* __restrict__ W2m, const float* __restrict__ W2v)
{
    int b = blockIdx.x;
    const float* src; __nv_bfloat16* dst; size_t base;
    if (b < 6144) { src = A; dst = g_abf; base = (size_t)b * 1024; }
    else {
        int r = b - 6144, w = r / 576, rb = r % 576;
        base = (size_t)rb * 1024;
        if      (w == 0) { src = W1m; dst = g_w1m; }
        else if (w == 1) { src = W1v; dst = g_w1v; }
        else if (w == 2) { src = W2m; dst = g_w2m; }
        else             { src = W2v; dst = g_w2v; }
    }
    size_t i = base + (size_t)threadIdx.x * 4;
    float4 v = *(const float4*)(src + i);
    __nv_bfloat162 lo = __floats2bfloat162_rn(v.x, v.y);
    __nv_bfloat162 hi = __floats2bfloat162_rn(v.z, v.w);
    *(uint2*)(dst + i) = make_uint2(*(uint32_t*)&lo, *(uint32_t*)&hi);
}

// ---------------------------------------------------------------------------
// HMMA primitives
__device__ __forceinline__ void ldsm_x4(uint32_t* r, uint32_t addr) {
    asm volatile("ldmatrix.sync.aligned.m8n8.x4.shared.b16 {%0,%1,%2,%3}, [%4];"
                 : "=r"(r[0]), "=r"(r[1]), "=r"(r[2]), "=r"(r[3]) : "r"(addr));
}
__device__ __forceinline__ void mma_bf16(float* c, const uint32_t* a, const uint32_t* b) {
    asm volatile(
        "mma.sync.aligned.m16n8k16.row.col.f32.bf16.bf16.f32 "
        "{%0,%1,%2,%3}, {%4,%5,%6,%7}, {%8,%9}, {%0,%1,%2,%3};"
        : "+f"(c[0]), "+f"(c[1]), "+f"(c[2]), "+f"(c[3])
        : "r"(a[0]), "r"(a[1]), "r"(a[2]), "r"(a[3]), "r"(b[0]), "r"(b[1]));
}
#define CP_ASYNC16(dst, src) \
    asm volatile("cp.async.cg.shared.global [%0], [%1], 16;" :: "r"(dst), "l"(src))
#define CP_COMMIT() asm volatile("cp.async.commit_group;" ::: "memory")
#define CP_WAIT1()  asm volatile("cp.async.wait_group 1;" ::: "memory")

// ---------------------------------------------------------------------------
// GEMM: C[M,N] = A[M,768] @ W[N,768]^T + bias, fused epilogues
// EPI 1: tanh -> bf16 out (gridDim.z selects {W0,b0,out0} / {W1,b1,out1})
// EPI 3: f32 mu out + per-CTA column sum/sumsq partials
// EPI 4: inv_var in regs, fused pos/neg partial reduction (no iv store)
// CTA 128x128, BK=64, 3-stage cp.async pipeline, 8 warps of 64x32.
#define GT_SMEM 98304   // 3 stages x (16KB A + 16KB W)

template <int EPI>
__global__ void __launch_bounds__(256, 2)
gemm_hmma(const __nv_bfloat16* __restrict__ A,
          const __nv_bfloat16* __restrict__ W0,
          const __nv_bfloat16* __restrict__ W1,
          const float* __restrict__ bias0,
          const float* __restrict__ bias1,
          void* __restrict__ out0,
          void* __restrict__ out1,
          const float* __restrict__ mbin)
{
    extern __shared__ char smem[];
    const uint32_t sb = smem_to_u32(smem);
    const int tid  = threadIdx.x;
    const int lane = tid & 31;
    const int wid  = tid >> 5;
    const int wm0  = (wid >> 2) * 64;
    const int wn0  = (wid & 3) * 32;
    const int bm   = blockIdx.y * 128;
    const int bn   = blockIdx.x * 128;

    const __nv_bfloat16* W = (EPI == 1 && blockIdx.z) ? W1 : W0;
    const float* bias      = (EPI == 1 && blockIdx.z) ? bias1 : bias0;
    void* Cout             = (EPI == 1 && blockIdx.z) ? out1 : out0;

    float acc[4][4][4];
#pragma unroll
    for (int i = 0; i < 4; i++)
#pragma unroll
        for (int j = 0; j < 4; j++)
#pragma unroll
            for (int q = 0; q < 4; q++) acc[i][j][q] = 0.f;

    const __nv_bfloat16* Ag = A + (size_t)bm * HD;
    const __nv_bfloat16* Wg = W + (size_t)bn * HD;

    // one 16B chunk per thread per row-quarter; xor-swizzled smem
    const int lrow = tid >> 3;        // 0..31
    const int lcg  = tid & 7;         // 16B group
    auto load_tiles = [&](int c, int stage) {
        const uint32_t ab = sb + stage * 32768;
        const uint32_t wb = ab + 16384;
        const int k0 = c * 64;
#pragma unroll
        for (int r = 0; r < 4; r++) {
            int row = r * 32 + lrow;
            uint32_t off = ((uint32_t)row << 7) + ((uint32_t)(lcg ^ (row & 7)) << 4);
            CP_ASYNC16(ab + off, Ag + (size_t)row * HD + k0 + lcg * 8);
            CP_ASYNC16(wb + off, Wg + (size_t)row * HD + k0 + lcg * 8);
        }
    };

    load_tiles(0, 0); CP_COMMIT();
    load_tiles(1, 1); CP_COMMIT();

    const int arow = lane & 15;
    const int ahi  = lane >> 4;
    const int bl8  = lane & 7;
    const int bsel = lane >> 3;

    for (int c = 0; c < 12; c++) {
        CP_WAIT1();            // chunk c resident
        __syncthreads();
        if (c + 2 < 12) load_tiles(c + 2, (c + 2) % 3);
        CP_COMMIT();           // keep group-count invariant

        const uint32_t ab = sb + (c % 3) * 32768;
        const uint32_t wb = ab + 16384;
#pragma unroll
        for (int ks = 0; ks < 4; ks++) {
            uint32_t afr[4][4];
#pragma unroll
            for (int mf = 0; mf < 4; mf++) {
                int row = wm0 + mf * 16 + arow;
                uint32_t addr = ab + ((uint32_t)row << 7)
                              + ((uint32_t)((2 * ks + ahi) ^ (row & 7)) << 4);
                ldsm_x4(afr[mf], addr);
            }
            uint32_t bfr[2][4];
#pragma unroll
            for (int nfp = 0; nfp < 2; nfp++) {
                int row = wn0 + nfp * 16 + ((bsel >> 1) << 3) + bl8;
                uint32_t addr = wb + ((uint32_t)row << 7)
                              + ((uint32_t)((2 * ks + (bsel & 1)) ^ (row & 7)) << 4);
                ldsm_x4(bfr[nfp], addr);
            }
#pragma unroll
            for (int nf = 0; nf < 4; nf++) {
                const uint32_t* bp = &bfr[nf >> 1][(nf & 1) * 2];
#pragma unroll
                for (int mf = 0; mf < 4; mf++)
                    mma_bf16(acc[mf][nf], afr[mf], bp);
            }
        }
        __syncthreads();
    }

    // ---------------- epilogues ----------------
    const int g  = lane >> 2;
    const int tq = lane & 3;

    if (EPI == 1) {
        __nv_bfloat16* C = (__nv_bfloat16*)Cout;
#pragma unroll
        for (int mf = 0; mf < 4; mf++) {
#pragma unroll
            for (int nf = 0; nf < 4; nf++) {
                const int m0 = bm + wm0 + mf * 16 + g;
                const int n  = bn + wn0 + nf * 8 + tq * 2;
                const float bv0 = __ldg(&bias[n]);
                const float bv1 = __ldg(&bias[n + 1]);
                __nv_bfloat162 p0 = __floats2bfloat162_rn(
                    tanhf(acc[mf][nf][0] + bv0), tanhf(acc[mf][nf][1] + bv1));
                __nv_bfloat162 p1 = __floats2bfloat162_rn(
                    tanhf(acc[mf][nf][2] + bv0), tanhf(acc[mf][nf][3] + bv1));
                *(__nv_bfloat162*)&C[(size_t)m0 * HD + n]       = p0;
                *(__nv_bfloat162*)&C[(size_t)(m0 + 8) * HD + n] = p1;
            }
        }
    } else if (EPI == 3) {
        // mu out (f32) + per-CTA column sum / sumsq partials
        float* C = (float*)Cout;
        float cs[4][2], cq[4][2];
#pragma unroll
        for (int nf = 0; nf < 4; nf++) { cs[nf][0]=cs[nf][1]=cq[nf][0]=cq[nf][1]=0.f; }
#pragma unroll
        for (int mf = 0; mf < 4; mf++) {
#pragma unroll
            for (int nf = 0; nf < 4; nf++) {
                const int m0 = bm + wm0 + mf * 16 + g;
                const int n  = bn + wn0 + nf * 8 + tq * 2;
                const float bv0 = __ldg(&bias[n]);
                const float bv1 = __ldg(&bias[n + 1]);
                float v00 = acc[mf][nf][0] + bv0;
                float v01 = acc[mf][nf][1] + bv1;
                float v10 = acc[mf][nf][2] + bv0;
                float v11 = acc[mf][nf][3] + bv1;
                *(float2*)&C[(size_t)m0 * HD + n]       = make_float2(v00, v01);
                *(float2*)&C[(size_t)(m0 + 8) * HD + n] = make_float2(v10, v11);
                cs[nf][0] += v00 + v10;  cq[nf][0] += v00*v00 + v10*v10;
                cs[nf][1] += v01 + v11;  cq[nf][1] += v01*v01 + v11*v11;
            }
        }
        // reduce over g-lanes (masks 4,8,16): per-warp 64-row column sums
#pragma unroll
        for (int msk = 4; msk <= 16; msk <<= 1) {
#pragma unroll
            for (int nf = 0; nf < 4; nf++) {
#pragma unroll
                for (int j = 0; j < 2; j++) {
                    cs[nf][j] += __shfl_xor_sync(0xffffffff, cs[nf][j], msk);
                    cq[nf][j] += __shfl_xor_sync(0xffffffff, cq[nf][j], msk);
                }
            }
        }
        __syncthreads();                      // smem free for reuse
        float* sred = (float*)smem;           // [mwarp][2][128]
        const int mwarp = wid >> 2;
        if (lane < 4) {
#pragma unroll
            for (int nf = 0; nf < 4; nf++) {
#pragma unroll
                for (int j = 0; j < 2; j++) {
                    int col = wn0 + nf * 8 + lane * 2 + j;
                    sred[(mwarp * 2 + 0) * 128 + col] = cs[nf][j];
                    sred[(mwarp * 2 + 1) * 128 + col] = cq[nf][j];
                }
            }
        }
        __syncthreads();
        if (tid < 128) {
            float s = sred[0 * 128 + tid] + sred[2 * 128 + tid];
            float q = sred[1 * 128 + tid] + sred[3 * 128 + tid];
            g_psum[blockIdx.y * HD + bn + tid] = s;
            g_psq [blockIdx.y * HD + bn + tid] = q;
        }
    } else {
        // EPI 4: inv_var in regs; fused positive/negative partial reduction
        float p = 0.f, nn = 0.f;
#pragma unroll
        for (int mf = 0; mf < 4; mf++) {
#pragma unroll
            for (int nf = 0; nf < 4; nf++) {
                const int m0 = bm + wm0 + mf * 16 + g;
                const int n  = bn + wn0 + nf * 8 + tq * 2;
                const float bv0 = __ldg(&bias[n]);
                const float bv1 = __ldg(&bias[n + 1]);
                float iv00 = __expf(-tanhf(acc[mf][nf][0] + bv0));
                float iv01 = __expf(-tanhf(acc[mf][nf][1] + bv1));
                float iv10 = __expf(-tanhf(acc[mf][nf][2] + bv0));
                float iv11 = __expf(-tanhf(acc[mf][nf][3] + bv1));
                float2 mu0 = *(const float2*)&g_mu[(size_t)m0 * HD + n];
                float2 mu1 = *(const float2*)&g_mu[(size_t)(m0 + 8) * HD + n];
                float2 mb0 = *(const float2*)&mbin[(size_t)m0 * HD + n];
                float2 mb1 = *(const float2*)&mbin[(size_t)(m0 + 8) * HD + n];
                float mn0 = __ldg(&g_mean[n]), mn1 = __ldg(&g_mean[n + 1]);
                float sq0 = __ldg(&g_sqm[n]),  sq1 = __ldg(&g_sqm[n + 1]);
                float d;
                d = mu0.x - mb0.x; p += d * d * iv00;
                d = mu0.y - mb0.y; p += d * d * iv01;
                d = mu1.x - mb1.x; p += d * d * iv10;
                d = mu1.y - mb1.y; p += d * d * iv11;
                nn += (sq0 - 2.f * mu0.x * mn0 + mu0.x * mu0.x) * iv00;
                nn += (sq1 - 2.f * mu0.y * mn1 + mu0.y * mu0.y) * iv01;
                nn += (sq0 - 2.f * mu1.x * mn0 + mu1.x * mu1.x) * iv10;
                nn += (sq1 - 2.f * mu1.y * mn1 + mu1.y * mu1.y) * iv11;
            }
        }
#pragma unroll
        for (int msk = 16; msk >= 1; msk >>= 1) {
            p  += __shfl_xor_sync(0xffffffff, p,  msk);
            nn += __shfl_xor_sync(0xffffffff, nn, msk);
        }
        __syncthreads();
        float* sred = (float*)smem;    // [16]
        if (lane == 0) { sred[wid] = p; sred[8 + wid] = nn; }
        __syncthreads();
        if (tid == 0) {
            float P = 0.f, Nn = 0.f;
#pragma unroll
            for (int w = 0; w < 8; w++) { P += sred[w]; Nn += sred[8 + w]; }
            int bid = blockIdx.y * gridDim.x + blockIdx.x;
            g_ppos[bid] = P;
            g_pneg[bid] = Nn;
        }
    }
}

// ---------------------------------------------------------------------------
__global__ void colsum_final()
{
    int h = blockIdx.x * 256 + threadIdx.x;    // 3 blocks x 256 = 768
    float s = 0.f, q = 0.f;
    for (int b = 0; b < 64; b++) {
        s += g_psum[b * HD + h];
        q += g_psq [b * HD + h];
    }
    g_mean[h] = s * (1.0f / MB_);
    g_sqm [h] = q * (1.0f / MB_);
}

__global__ void finalize(float* __restrict__ out)
{
    __shared__ float sp[256], sn[256];
    int t = threadIdx.x;
    float p = 0.f, n = 0.f;
    for (int i = t; i < 384; i += 256) { p += g_ppos[i]; n += g_pneg[i]; }
    sp[t] = p; sn[t] = n;
    __syncthreads();
    for (int s = 128; s > 0; s >>= 1) {
        if (t < s) { sp[t] += sp[t + s]; sn[t] += sn[t + s]; }
        __syncthreads();
    }
    if (t == 0) {
        float P = sp[0], Nn = sn[0];
        out[0] = -0.5f * P / (float)MB_;
        out[1] = 0.5f * (Nn - P) / (float)MB_;
    }
}

// ---------------------------------------------------------------------------
extern "C" void kernel_launch(void* const* d_in, const int* in_sizes, int n_in,
                              void* d_out, int out_size)
{
    const float* A   = (const float*)d_in[0];
    const float* Mb  = (const float*)d_in[1];
    const float* W1m = (const float*)d_in[2];
    const float* b1m = (const float*)d_in[3];
    const float* W2m = (const float*)d_in[4];
    const float* b2m = (const float*)d_in[5];
    const float* W1v = (const float*)d_in[6];
    const float* b1v = (const float*)d_in[7];
    const float* W2v = (const float*)d_in[8];
    const float* b2v = (const float*)d_in[9];

    __nv_bfloat16 *abf, *w1m, *w1v, *w2m, *w2v, *t1m, *t1v;
    float *mu;
    cudaGetSymbolAddress((void**)&abf, g_abf);
    cudaGetSymbolAddress((void**)&w1m, g_w1m);
    cudaGetSymbolAddress((void**)&w1v, g_w1v);
    cudaGetSymbolAddress((void**)&w2m, g_w2m);
    cudaGetSymbolAddress((void**)&w2v, g_w2v);
    cudaGetSymbolAddress((void**)&t1m, g_t1m);
    cudaGetSymbolAddress((void**)&t1v, g_t1v);
    cudaGetSymbolAddress((void**)&mu,  g_mu);

    cudaFuncSetAttribute(gemm_hmma<1>, cudaFuncAttributeMaxDynamicSharedMemorySize, GT_SMEM);
    cudaFuncSetAttribute(gemm_hmma<3>, cudaFuncAttributeMaxDynamicSharedMemorySize, GT_SMEM);
    cudaFuncSetAttribute(gemm_hmma<4>, cudaFuncAttributeMaxDynamicSharedMemorySize, GT_SMEM);

    cvt_all<<<6144 + 4 * 576, 256>>>(A, W1m, W1v, W2m, W2v);

    dim3 grid12(HD / 128, MB_ / 128, 2);  // (6, 64, 2)
    gemm_hmma<1><<<grid12, 256, GT_SMEM>>>(abf, w1m, w1v, b1m, b1v, t1m, t1v, nullptr);

    dim3 grid(HD / 128, MB_ / 128);       // (6, 64)
    gemm_hmma<3><<<grid, 256, GT_SMEM>>>(t1m, w2m, w2m, b2m, b2m, mu, mu, nullptr);
    colsum_final<<<3, 256>>>();
    gemm_hmma<4><<<grid, 256, GT_SMEM>>>(t1v, w2v, w2v, b2v, b2v, nullptr, nullptr, Mb);
    finalize<<<1, 256>>>((float*)d_out);
}

// round 5
// speedup vs baseline: 7.0647x; 1.0702x over previous
#include <cuda_runtime.h>
#include <cuda_bf16.h>
#include <cstdint>
#include <math.h>

// ---------------------------------------------------------------------------
#define MB_ 8192   // batch B
#define HD  768    // hidden H (= K dim)

__device__ __forceinline__ uint32_t smem_to_u32(const void* smem_ptr) {
    uint32_t addr;
    asm("{ .reg .u64 tmp; cvta.to.shared.u64 tmp, %1; cvt.u32.u64 %0, tmp; }"
        : "=r"(addr) : "l"(smem_ptr));
    return addr;
}

// ---------------------------------------------------------------------------
// scratch (device globals; no allocation allowed)
__device__ __nv_bfloat16 g_abf [MB_ * HD];
__device__ __nv_bfloat16 g_w1m [HD * HD];
__device__ __nv_bfloat16 g_w1v [HD * HD];
__device__ __nv_bfloat16 g_w2m [HD * HD];
__device__ __nv_bfloat16 g_w2v [HD * HD];
__device__ __nv_bfloat16 g_t1m [MB_ * HD];
__device__ __nv_bfloat16 g_t1v [MB_ * HD];
__device__ float g_psum  [64 * HD];   // per m-block column sums of mu
__device__ float g_psq   [64 * HD];   // per m-block column sums of mu^2
__device__ float g_siv   [64 * HD];   // per m-block column sums of iv
__device__ float g_smuiv [64 * HD];   // per m-block column sums of mu*iv
__device__ float g_ppos  [384];       // per-CTA sum (mu-b)^2*iv
__device__ float g_pm2   [384];       // per-CTA sum mu^2*iv
__device__ float g_negp  [24];        // per-fc1-block negative partials

// ---------------------------------------------------------------------------
// all fp32->bf16 conversions in one launch
__global__ void cvt_all(const float* __restrict__ A,
                        const float* __restrict__ W1m, const float* __restrict__ W1v,
                        const float* __restrict__ W2m, const float* __restrict__ W2v)
{
    int b = blockIdx.x;
    const float* src; __nv_bfloat16* dst; size_t base;
    if (b < 6144) { src = A; dst = g_abf; base = (size_t)b * 1024; }
    else {
        int r = b - 6144, w = r / 576, rb = r % 576;
        base = (size_t)rb * 1024;
        if      (w == 0) { src = W1m; dst = g_w1m; }
        else if (w == 1) { src = W1v; dst = g_w1v; }
        else if (w == 2) { src = W2m; dst = g_w2m; }
        else             { src = W2v; dst = g_w2v; }
    }
    size_t i = base + (size_t)threadIdx.x * 4;
    float4 v = *(const float4*)(src + i);
    __nv_bfloat162 lo = __floats2bfloat162_rn(v.x, v.y);
    __nv_bfloat162 hi = __floats2bfloat162_rn(v.z, v.w);
    *(uint2*)(dst + i) = make_uint2(*(uint32_t*)&lo, *(uint32_t*)&hi);
}

// ---------------------------------------------------------------------------
// HMMA primitives
__device__ __forceinline__ void ldsm_x4(uint32_t* r, uint32_t addr) {
    asm volatile("ldmatrix.sync.aligned.m8n8.x4.shared.b16 {%0,%1,%2,%3}, [%4];"
                 : "=r"(r[0]), "=r"(r[1]), "=r"(r[2]), "=r"(r[3]) : "r"(addr));
}
__device__ __forceinline__ void mma_bf16(float* c, const uint32_t* a, const uint32_t* b) {
    asm volatile(
        "mma.sync.aligned.m16n8k16.row.col.f32.bf16.bf16.f32 "
        "{%0,%1,%2,%3}, {%4,%5,%6,%7}, {%8,%9}, {%0,%1,%2,%3};"
        : "+f"(c[0]), "+f"(c[1]), "+f"(c[2]), "+f"(c[3])
        : "r"(a[0]), "r"(a[1]), "r"(a[2]), "r"(a[3]), "r"(b[0]), "r"(b[1]));
}
#define CP_ASYNC16(dst, src) \
    asm volatile("cp.async.cg.shared.global [%0], [%1], 16;" :: "r"(dst), "l"(src))
#define CP_COMMIT() asm volatile("cp.async.commit_group;" ::: "memory")
#define CP_WAIT1()  asm volatile("cp.async.wait_group 1;" ::: "memory")

// ---------------------------------------------------------------------------
// GEMM1+2: C = tanh(A@W^T + b) -> bf16, gridDim.z selects (W1m,b1m,t1m)/(W1v,b1v,t1v)
// CTA 128x128, BK=64, 3-stage cp.async, 8 warps of 64x32.
#define GT_SMEM 98304

__global__ void __launch_bounds__(256, 2)
gemm_tanh(const __nv_bfloat16* __restrict__ A,
          const __nv_bfloat16* __restrict__ W0,
          const __nv_bfloat16* __restrict__ W1,
          const float* __restrict__ bias0,
          const float* __restrict__ bias1,
          __nv_bfloat16* __restrict__ out0,
          __nv_bfloat16* __restrict__ out1)
{
    extern __shared__ char smem[];
    const uint32_t sb = smem_to_u32(smem);
    const int tid  = threadIdx.x;
    const int lane = tid & 31;
    const int wid  = tid >> 5;
    const int wm0  = (wid >> 2) * 64;
    const int wn0  = (wid & 3) * 32;
    const int bm   = blockIdx.y * 128;
    const int bn   = blockIdx.x * 128;

    const __nv_bfloat16* W = blockIdx.z ? W1 : W0;
    const float* bias      = blockIdx.z ? bias1 : bias0;
    __nv_bfloat16* C       = blockIdx.z ? out1 : out0;

    float acc[4][4][4];
#pragma unroll
    for (int i = 0; i < 4; i++)
#pragma unroll
        for (int j = 0; j < 4; j++)
#pragma unroll
            for (int q = 0; q < 4; q++) acc[i][j][q] = 0.f;

    const __nv_bfloat16* Ag = A + (size_t)bm * HD;
    const __nv_bfloat16* Wg = W + (size_t)bn * HD;

    const int lrow = tid >> 3;
    const int lcg  = tid & 7;
    auto load_tiles = [&](int c, int stage) {
        const uint32_t ab = sb + stage * 32768;
        const uint32_t wb = ab + 16384;
        const int k0 = c * 64;
#pragma unroll
        for (int r = 0; r < 4; r++) {
            int row = r * 32 + lrow;
            uint32_t off = ((uint32_t)row << 7) + ((uint32_t)(lcg ^ (row & 7)) << 4);
            CP_ASYNC16(ab + off, Ag + (size_t)row * HD + k0 + lcg * 8);
            CP_ASYNC16(wb + off, Wg + (size_t)row * HD + k0 + lcg * 8);
        }
    };

    load_tiles(0, 0); CP_COMMIT();
    load_tiles(1, 1); CP_COMMIT();

    const int arow = lane & 15;
    const int ahi  = lane >> 4;
    const int bl8  = lane & 7;
    const int bsel = lane >> 3;

    for (int c = 0; c < 12; c++) {
        CP_WAIT1();
        __syncthreads();
        if (c + 2 < 12) load_tiles(c + 2, (c + 2) % 3);
        CP_COMMIT();

        const uint32_t ab = sb + (c % 3) * 32768;
        const uint32_t wb = ab + 16384;
#pragma unroll
        for (int ks = 0; ks < 4; ks++) {
            uint32_t afr[4][4];
#pragma unroll
            for (int mf = 0; mf < 4; mf++) {
                int row = wm0 + mf * 16 + arow;
                uint32_t addr = ab + ((uint32_t)row << 7)
                              + ((uint32_t)((2 * ks + ahi) ^ (row & 7)) << 4);
                ldsm_x4(afr[mf], addr);
            }
            uint32_t bfr[2][4];
#pragma unroll
            for (int nfp = 0; nfp < 2; nfp++) {
                int row = wn0 + nfp * 16 + ((bsel >> 1) << 3) + bl8;
                uint32_t addr = wb + ((uint32_t)row << 7)
                              + ((uint32_t)((2 * ks + (bsel & 1)) ^ (row & 7)) << 4);
                ldsm_x4(bfr[nfp], addr);
            }
#pragma unroll
            for (int nf = 0; nf < 4; nf++) {
                const uint32_t* bp = &bfr[nf >> 1][(nf & 1) * 2];
#pragma unroll
                for (int mf = 0; mf < 4; mf++)
                    mma_bf16(acc[mf][nf], afr[mf], bp);
            }
        }
        __syncthreads();
    }

    const int g  = lane >> 2;
    const int tq = lane & 3;
#pragma unroll
    for (int mf = 0; mf < 4; mf++) {
#pragma unroll
        for (int nf = 0; nf < 4; nf++) {
            const int m0 = bm + wm0 + mf * 16 + g;
            const int n  = bn + wn0 + nf * 8 + tq * 2;
            const float bv0 = __ldg(&bias[n]);
            const float bv1 = __ldg(&bias[n + 1]);
            __nv_bfloat162 p0 = __floats2bfloat162_rn(
                tanhf(acc[mf][nf][0] + bv0), tanhf(acc[mf][nf][1] + bv1));
            __nv_bfloat162 p1 = __floats2bfloat162_rn(
                tanhf(acc[mf][nf][2] + bv0), tanhf(acc[mf][nf][3] + bv1));
            *(__nv_bfloat162*)&C[(size_t)m0 * HD + n]       = p0;
            *(__nv_bfloat162*)&C[(size_t)(m0 + 8) * HD + n] = p1;
        }
    }
}

// ---------------------------------------------------------------------------
// Fused GEMM3+GEMM4: per CTA (128x128 tile):
//  loop1: mu = t1m@W2m^T + b2m  -> bf16 tile in smem + column S_mu/S_mu2 partials
//  loop2: z  = t1v@W2v^T + b2v; iv = exp(-tanh(z)) in regs;
//         accumulate P=(mu-b)^2*iv, M2=mu^2*iv (scalars), S_iv/S_muiv (columns)
// 2-stage cp.async pipeline (64KB) + mu tile (33.75KB) + staging.
#define FU_PIPE   65536
#define FU_MU     65536              // mu tile offset
#define FU_MUSTR  264                // padded row stride (bytes)
#define FU_STG    (65536 + 33792)    // staging offset
#define FU_SMEM   (65536 + 33792 + 2176)

__device__ __forceinline__ void fused_mainloop(
    uint32_t sb, const __nv_bfloat16* __restrict__ Ag,
    const __nv_bfloat16* __restrict__ Wg,
    int tid, int lane, int wm0, int wn0, float acc[4][4][4])
{
    const int lrow = tid >> 3;
    const int lcg  = tid & 7;
    auto load_tiles = [&](int c, int stage) {
        const uint32_t ab = sb + stage * 32768;
        const uint32_t wb = ab + 16384;
        const int k0 = c * 64;
#pragma unroll
        for (int r = 0; r < 4; r++) {
            int row = r * 32 + lrow;
            uint32_t off = ((uint32_t)row << 7) + ((uint32_t)(lcg ^ (row & 7)) << 4);
            CP_ASYNC16(ab + off, Ag + (size_t)row * HD + k0 + lcg * 8);
            CP_ASYNC16(wb + off, Wg + (size_t)row * HD + k0 + lcg * 8);
        }
    };

    load_tiles(0, 0); CP_COMMIT();
    load_tiles(1, 1); CP_COMMIT();

    const int arow = lane & 15;
    const int ahi  = lane >> 4;
    const int bl8  = lane & 7;
    const int bsel = lane >> 3;

    for (int c = 0; c < 12; c++) {
        CP_WAIT1();                      // chunk c resident
        __syncthreads();
        const uint32_t ab = sb + (c & 1) * 32768;
        const uint32_t wb = ab + 16384;
#pragma unroll
        for (int ks = 0; ks < 4; ks++) {
            uint32_t afr[4][4];
#pragma unroll
            for (int mf = 0; mf < 4; mf++) {
                int row = wm0 + mf * 16 + arow;
                uint32_t addr = ab + ((uint32_t)row << 7)
                              + ((uint32_t)((2 * ks + ahi) ^ (row & 7)) << 4);
                ldsm_x4(afr[mf], addr);
            }
            uint32_t bfr[2][4];
#pragma unroll
            for (int nfp = 0; nfp < 2; nfp++) {
                int row = wn0 + nfp * 16 + ((bsel >> 1) << 3) + bl8;
                uint32_t addr = wb + ((uint32_t)row << 7)
                              + ((uint32_t)((2 * ks + (bsel & 1)) ^ (row & 7)) << 4);
                ldsm_x4(bfr[nfp], addr);
            }
#pragma unroll
            for (int nf = 0; nf < 4; nf++) {
                const uint32_t* bp = &bfr[nf >> 1][(nf & 1) * 2];
#pragma unroll
                for (int mf = 0; mf < 4; mf++)
                    mma_bf16(acc[mf][nf], afr[mf], bp);
            }
        }
        __syncthreads();                 // all warps done with stage c&1
        if (c + 2 < 12) load_tiles(c + 2, c & 1);
        CP_COMMIT();                     // keep group-count invariant
    }
}

__global__ void __launch_bounds__(256, 2)
gemm_fused34(const __nv_bfloat16* __restrict__ A1,   // t1m
             const __nv_bfloat16* __restrict__ Wm,   // w2m
             const float* __restrict__ bm_,
             const __nv_bfloat16* __restrict__ A2,   // t1v
             const __nv_bfloat16* __restrict__ Wv,   // w2v
             const float* __restrict__ bv_,
             const float* __restrict__ mbin)
{
    extern __shared__ char smem[];
    const uint32_t sb = smem_to_u32(smem);
    const int tid  = threadIdx.x;
    const int lane = tid & 31;
    const int wid  = tid >> 5;
    const int wm0  = (wid >> 2) * 64;
    const int wn0  = (wid & 3) * 32;
    const int bm   = blockIdx.y * 128;
    const int bn   = blockIdx.x * 128;
    const int g    = lane >> 2;
    const int tq   = lane & 3;
    const int mwarp = wid >> 2;

    float acc[4][4][4];
#pragma unroll
    for (int i = 0; i < 4; i++)
#pragma unroll
        for (int j = 0; j < 4; j++)
#pragma unroll
            for (int q = 0; q < 4; q++) acc[i][j][q] = 0.f;

    // ---- loop 1: mu ----
    fused_mainloop(sb, A1 + (size_t)bm * HD, Wm + (size_t)bn * HD,
                   tid, lane, wm0, wn0, acc);

    // ---- epilogue 1: mu -> smem bf16 + column S_mu / S_mu2 partials ----
    {
        float cs[4][2], cq[4][2];
#pragma unroll
        for (int nf = 0; nf < 4; nf++) { cs[nf][0]=cs[nf][1]=cq[nf][0]=cq[nf][1]=0.f; }
#pragma unroll
        for (int mf = 0; mf < 4; mf++) {
#pragma unroll
            for (int nf = 0; nf < 4; nf++) {
                const int ml = wm0 + mf * 16 + g;
                const int n  = bn + wn0 + nf * 8 + tq * 2;
                const int nl = wn0 + nf * 8 + tq * 2;
                const float bv0 = __ldg(&bm_[n]);
                const float bv1 = __ldg(&bm_[n + 1]);
                float v00 = acc[mf][nf][0] + bv0;
                float v01 = acc[mf][nf][1] + bv1;
                float v10 = acc[mf][nf][2] + bv0;
                float v11 = acc[mf][nf][3] + bv1;
                __nv_bfloat162 p0 = __floats2bfloat162_rn(v00, v01);
                __nv_bfloat162 p1 = __floats2bfloat162_rn(v10, v11);
                *(__nv_bfloat162*)(smem + FU_MU + ml * FU_MUSTR + nl * 2)       = p0;
                *(__nv_bfloat162*)(smem + FU_MU + (ml + 8) * FU_MUSTR + nl * 2) = p1;
                cs[nf][0] += v00 + v10;  cq[nf][0] += v00*v00 + v10*v10;
                cs[nf][1] += v01 + v11;  cq[nf][1] += v01*v01 + v11*v11;
            }
        }
#pragma unroll
        for (int msk = 4; msk <= 16; msk <<= 1)
#pragma unroll
            for (int nf = 0; nf < 4; nf++)
#pragma unroll
                for (int j = 0; j < 2; j++) {
                    cs[nf][j] += __shfl_xor_sync(0xffffffff, cs[nf][j], msk);
                    cq[nf][j] += __shfl_xor_sync(0xffffffff, cq[nf][j], msk);
                }
        float* sred = (float*)(smem + FU_STG);   // [mwarp][2][128]
        if (lane < 4) {
#pragma unroll
            for (int nf = 0; nf < 4; nf++)
#pragma unroll
                for (int j = 0; j < 2; j++) {
                    int col = wn0 + nf * 8 + lane * 2 + j;
                    sred[(mwarp * 2 + 0) * 128 + col] = cs[nf][j];
                    sred[(mwarp * 2 + 1) * 128 + col] = cq[nf][j];
                }
        }
        __syncthreads();
        if (tid < 128) {
            g_psum[blockIdx.y * HD + bn + tid] = sred[0 * 128 + tid] + sred[2 * 128 + tid];
            g_psq [blockIdx.y * HD + bn + tid] = sred[1 * 128 + tid] + sred[3 * 128 + tid];
        }
        __syncthreads();
    }

    // ---- loop 2: iv pre-activation ----
#pragma unroll
    for (int i = 0; i < 4; i++)
#pragma unroll
        for (int j = 0; j < 4; j++)
#pragma unroll
            for (int q = 0; q < 4; q++) acc[i][j][q] = 0.f;

    fused_mainloop(sb, A2 + (size_t)bm * HD, Wv + (size_t)bn * HD,
                   tid, lane, wm0, wn0, acc);

    // ---- epilogue 2: P, M2 scalars + S_iv / S_muiv column partials ----
    {
        float p = 0.f, m2 = 0.f;
        float ci[4][2], cm[4][2];
#pragma unroll
        for (int nf = 0; nf < 4; nf++) { ci[nf][0]=ci[nf][1]=cm[nf][0]=cm[nf][1]=0.f; }
#pragma unroll
        for (int mf = 0; mf < 4; mf++) {
#pragma unroll
            for (int nf = 0; nf < 4; nf++) {
                const int ml = wm0 + mf * 16 + g;
                const int m0 = bm + ml;
                const int n  = bn + wn0 + nf * 8 + tq * 2;
                const int nl = wn0 + nf * 8 + tq * 2;
                const float bv0 = __ldg(&bv_[n]);
                const float bv1 = __ldg(&bv_[n + 1]);
                float iv00 = __expf(-tanhf(acc[mf][nf][0] + bv0));
                float iv01 = __expf(-tanhf(acc[mf][nf][1] + bv1));
                float iv10 = __expf(-tanhf(acc[mf][nf][2] + bv0));
                float iv11 = __expf(-tanhf(acc[mf][nf][3] + bv1));
                __nv_bfloat162 q0 = *(__nv_bfloat162*)(smem + FU_MU + ml * FU_MUSTR + nl * 2);
                __nv_bfloat162 q1 = *(__nv_bfloat162*)(smem + FU_MU + (ml + 8) * FU_MUSTR + nl * 2);
                float mu00 = __bfloat162float(q0.x), mu01 = __bfloat162float(q0.y);
                float mu10 = __bfloat162float(q1.x), mu11 = __bfloat162float(q1.y);
                float2 mb0 = *(const float2*)&mbin[(size_t)m0 * HD + n];
                float2 mb1 = *(const float2*)&mbin[(size_t)(m0 + 8) * HD + n];
                float d;
                d = mu00 - mb0.x; p += d * d * iv00;
                d = mu01 - mb0.y; p += d * d * iv01;
                d = mu10 - mb1.x; p += d * d * iv10;
                d = mu11 - mb1.y; p += d * d * iv11;
                m2 += mu00*mu00*iv00 + mu01*mu01*iv01 + mu10*mu10*iv10 + mu11*mu11*iv11;
                ci[nf][0] += iv00 + iv10;          ci[nf][1] += iv01 + iv11;
                cm[nf][0] += mu00*iv00 + mu10*iv10; cm[nf][1] += mu01*iv01 + mu11*iv11;
            }
        }
        // column partial reduce over g-lanes
#pragma unroll
        for (int msk = 4; msk <= 16; msk <<= 1)
#pragma unroll
            for (int nf = 0; nf < 4; nf++)
#pragma unroll
                for (int j = 0; j < 2; j++) {
                    ci[nf][j] += __shfl_xor_sync(0xffffffff, ci[nf][j], msk);
                    cm[nf][j] += __shfl_xor_sync(0xffffffff, cm[nf][j], msk);
                }
        // scalar full-warp reduce
#pragma unroll
        for (int msk = 16; msk >= 1; msk >>= 1) {
            p  += __shfl_xor_sync(0xffffffff, p,  msk);
            m2 += __shfl_xor_sync(0xffffffff, m2, msk);
        }
        float* sred = (float*)(smem + FU_STG);   // [mwarp][2][128] + 16 scalars
        float* ssc  = sred + 512;
        if (lane < 4) {
#pragma unroll
            for (int nf = 0; nf < 4; nf++)
#pragma unroll
                for (int j = 0; j < 2; j++) {
                    int col = wn0 + nf * 8 + lane * 2 + j;
                    sred[(mwarp * 2 + 0) * 128 + col] = ci[nf][j];
                    sred[(mwarp * 2 + 1) * 128 + col] = cm[nf][j];
                }
        }
        if (lane == 0) { ssc[wid] = p; ssc[8 + wid] = m2; }
        __syncthreads();
        if (tid < 128) {
            g_siv  [blockIdx.y * HD + bn + tid] = sred[0 * 128 + tid] + sred[2 * 128 + tid];
            g_smuiv[blockIdx.y * HD + bn + tid] = sred[1 * 128 + tid] + sred[3 * 128 + tid];
        }
        if (tid == 0) {
            float P = 0.f, M2 = 0.f;
#pragma unroll
            for (int w = 0; w < 8; w++) { P += ssc[w]; M2 += ssc[8 + w]; }
            int bid = blockIdx.y * gridDim.x + blockIdx.x;
            g_ppos[bid] = P;
            g_pm2 [bid] = M2;
        }
    }
}

// ---------------------------------------------------------------------------
// fc1: reduce 64 m-block slabs per column; compute per-column negative term
// grid 24 x 256: block handles 32 columns, 8 threads per column.
__global__ void fc1()
{
    const int tid = threadIdx.x;
    const int col_l = tid >> 3;        // 0..31
    const int sg    = tid & 7;         // slab group
    const int h = blockIdx.x * 32 + col_l;
    float smu = 0.f, sm2 = 0.f, siv = 0.f, smv = 0.f;
#pragma unroll
    for (int s = 0; s < 8; s++) {
        int idx = (sg * 8 + s) * HD + h;
        smu += g_psum[idx]; sm2 += g_psq[idx];
        siv += g_siv[idx];  smv += g_smuiv[idx];
    }
#pragma unroll
    for (int msk = 1; msk <= 4; msk <<= 1) {
        smu += __shfl_xor_sync(0xffffffff, smu, msk);
        sm2 += __shfl_xor_sync(0xffffffff, sm2, msk);
        siv += __shfl_xor_sync(0xffffffff, siv, msk);
        smv += __shfl_xor_sync(0xffffffff, smv, msk);
    }
    __shared__ float s_neg[32];
    if (sg == 0) {
        float mean = smu * (1.0f / MB_);
        float sqm  = sm2 * (1.0f / MB_);
        s_neg[col_l] = sqm * siv - 2.0f * mean * smv;
    }
    __syncthreads();
    if (tid < 32) {
        float v = s_neg[tid];
#pragma unroll
        for (int msk = 16; msk >= 1; msk >>= 1)
            v += __shfl_xor_sync(0xffffffff, v, msk);
        if (tid == 0) g_negp[blockIdx.x] = v;
    }
}

// fc2: final scalars
__global__ void fc2(float* __restrict__ out)
{
    const int tid = threadIdx.x;       // 128 threads
    float p = 0.f, m2 = 0.f, ng = 0.f;
    for (int i = tid; i < 384; i += 128) { p += g_ppos[i]; m2 += g_pm2[i]; }
    if (tid < 24) ng = g_negp[tid];
    __shared__ float sp[128], sm[128], sg_[128];
    sp[tid] = p; sm[tid] = m2; sg_[tid] = ng;
    __syncthreads();
    for (int s = 64; s > 0; s >>= 1) {
        if (tid < s) { sp[tid] += sp[tid+s]; sm[tid] += sm[tid+s]; sg_[tid] += sg_[tid+s]; }
        __syncthreads();
    }
    if (tid == 0) {
        float P = sp[0];
        float N = sg_[0] + sm[0];
        out[0] = -0.5f * P / (float)MB_;
        out[1] = 0.5f * (N - P) / (float)MB_;
    }
}

// ---------------------------------------------------------------------------
extern "C" void kernel_launch(void* const* d_in, const int* in_sizes, int n_in,
                              void* d_out, int out_size)
{
    const float* A   = (const float*)d_in[0];
    const float* Mb  = (const float*)d_in[1];
    const float* W1m = (const float*)d_in[2];
    const float* b1m = (const float*)d_in[3];
    const float* W2m = (const float*)d_in[4];
    const float* b2m = (const float*)d_in[5];
    const float* W1v = (const float*)d_in[6];
    const float* b1v = (const float*)d_in[7];
    const float* W2v = (const float*)d_in[8];
    const float* b2v = (const float*)d_in[9];

    __nv_bfloat16 *abf, *w1m, *w1v, *w2m, *w2v, *t1m, *t1v;
    cudaGetSymbolAddress((void**)&abf, g_abf);
    cudaGetSymbolAddress((void**)&w1m, g_w1m);
    cudaGetSymbolAddress((void**)&w1v, g_w1v);
    cudaGetSymbolAddress((void**)&w2m, g_w2m);
    cudaGetSymbolAddress((void**)&w2v, g_w2v);
    cudaGetSymbolAddress((void**)&t1m, g_t1m);
    cudaGetSymbolAddress((void**)&t1v, g_t1v);

    cudaFuncSetAttribute(gemm_tanh,    cudaFuncAttributeMaxDynamicSharedMemorySize, GT_SMEM);
    cudaFuncSetAttribute(gemm_fused34, cudaFuncAttributeMaxDynamicSharedMemorySize, FU_SMEM);

    cvt_all<<<6144 + 4 * 576, 256>>>(A, W1m, W1v, W2m, W2v);

    dim3 grid12(HD / 128, MB_ / 128, 2);  // (6, 64, 2)
    gemm_tanh<<<grid12, 256, GT_SMEM>>>(abf, w1m, w1v, b1m, b1v, t1m, t1v);

    dim3 grid(HD / 128, MB_ / 128);       // (6, 64)
    gemm_fused34<<<grid, 256, FU_SMEM>>>(t1m, w2m, b2m, t1v, w2v, b2v, Mb);

    fc1<<<24, 256>>>();
    fc2<<<1, 128>>>((float*)d_out);
}